// round 2
// baseline (speedup 1.0000x reference)
#include <cuda_runtime.h>
#include <cuda_bf16.h>

// ---------------------------------------------------------------------------
// SchNet interaction block, GB300 sm_103a — FFMA2 (fma.rn.f32x2) pipeline v2.
//   K1: XF = x @ W_in2f                                   (gemm32)
//   K2: per-atom fused filter MLP + gather + aggregate    (fused_filter)
//   K3: out = ssp((Y@W_f2out+b_f2out)@W_dense + G@W_ang + b_dense)  (tail)
// v2: double-buffered weight staging (1 sync/tile), neighbor compaction
//     with interleaved row ownership, fused tail, 32-row small GEMMs.
// ---------------------------------------------------------------------------

#define BDIM 256
#define NB   64
#define KS   128
#define NF   256
#define NATOMS 4096
#define CUTOFF 5.0f

__device__ float g_XF[NATOMS * NF];
__device__ float g_Y [NATOMS * NF];

// ---- packed f32x2 helpers --------------------------------------------------

__device__ __forceinline__ void fma2(unsigned long long& d,
                                     unsigned long long a,
                                     unsigned long long b) {
    asm("fma.rn.f32x2 %0, %1, %2, %3;" : "=l"(d) : "l"(a), "l"(b), "l"(d));
}
__device__ __forceinline__ unsigned long long pack_dup(float v) {
    unsigned long long r;
    asm("mov.b64 %0, {%1, %1};" : "=l"(r) : "f"(v));
    return r;
}
__device__ __forceinline__ float2 unpack2(unsigned long long u) {
    float2 r;
    asm("mov.b64 {%0, %1}, %2;" : "=f"(r.x), "=f"(r.y) : "l"(u));
    return r;
}
__device__ __forceinline__ float sspf(float v) {
    float e = __expf(v);
    float r = __logf(fmaf(0.5f, e, 0.5f));
    return (v > 60.0f) ? (v - 0.69314718055994531f) : r;
}

// one 8-deep K step from a staged 8x256 weight tile, JROWS consecutive rows
template<int JROWS>
__device__ __forceinline__ void mma_step(const float* cur, const float* sAk,
                                         int lda, int rowbase, int f0,
                                         unsigned long long (&acc)[JROWS][4])
{
    #pragma unroll
    for (int kk = 0; kk < 8; ++kk) {
        ulonglong2 bva = *(const ulonglong2*)&cur[kk * 256 + f0];
        ulonglong2 bvb = *(const ulonglong2*)&cur[kk * 256 + f0 + 4];
        #pragma unroll
        for (int j = 0; j < JROWS; ++j) {
            unsigned long long a2 = pack_dup(sAk[(rowbase + j) * lda + kk]);
            fma2(acc[j][0], a2, bva.x);
            fma2(acc[j][1], a2, bva.y);
            fma2(acc[j][2], a2, bvb.x);
            fma2(acc[j][3], a2, bvb.y);
        }
    }
}

// ---- K1: 32-row GEMM, C = A @ W  (K=256, N=256) ----------------------------

__global__ __launch_bounds__(BDIM, 2)
void gemm32_kernel(const float* __restrict__ A,
                   const float* __restrict__ W,
                   float* __restrict__ C)
{
    extern __shared__ float smem[];
    float* sA  = smem;           // 32*256 = 8192
    float* sWa = smem + 8192;    // 2048
    float* sWb = smem + 10240;   // 2048

    const int tid = threadIdx.x;
    const int tn  = tid >> 5;
    const int f0  = (tid & 31) * 8;
    const int r0  = tn * 4;

    {
        const float* src = A + (size_t)blockIdx.x * 32 * 256;
        #pragma unroll
        for (int u = 0; u < 8; ++u)
            *(float4*)&sA[tid * 4 + u * 1024] = *(const float4*)&src[tid * 4 + u * 1024];
    }
    *(float4*)&sWa[tid * 8]     = *(const float4*)&W[tid * 8];
    *(float4*)&sWa[tid * 8 + 4] = *(const float4*)&W[tid * 8 + 4];
    __syncthreads();

    unsigned long long acc[4][4];
    #pragma unroll
    for (int j = 0; j < 4; ++j)
        #pragma unroll
        for (int i = 0; i < 4; ++i) acc[j][i] = 0ull;

    #pragma unroll 1
    for (int k0 = 0; k0 < 256; k0 += 8) {
        const float* cur = ((k0 >> 3) & 1) ? sWb : sWa;
        float*       nxt = ((k0 >> 3) & 1) ? sWa : sWb;
        float4 p0, p1;
        const bool more = (k0 + 8) < 256;
        if (more) {
            p0 = *(const float4*)&W[(k0 + 8) * 256 + tid * 8];
            p1 = *(const float4*)&W[(k0 + 8) * 256 + tid * 8 + 4];
        }
        mma_step<4>(cur, sA + k0, 256, r0, f0, acc);
        if (more) {
            *(float4*)&nxt[tid * 8]     = p0;
            *(float4*)&nxt[tid * 8 + 4] = p1;
        }
        __syncthreads();
    }

    #pragma unroll
    for (int j = 0; j < 4; ++j) {
        float w[8];
        #pragma unroll
        for (int i2 = 0; i2 < 4; ++i2) {
            float2 v = unpack2(acc[j][i2]);
            w[2*i2] = v.x; w[2*i2+1] = v.y;
        }
        const int row = blockIdx.x * 32 + r0 + j;
        *(float4*)&C[(size_t)row * 256 + f0]     = make_float4(w[0], w[1], w[2], w[3]);
        *(float4*)&C[(size_t)row * 256 + f0 + 4] = make_float4(w[4], w[5], w[6], w[7]);
    }
}

// ---- K2: fused filter MLP + gather + aggregate, 1 CTA per atom -------------
// smem layout (floats):
//   [0,8192)      sF: compacted f_ij [64][128]; during GEMM2 first 4096 floats
//                 are reused as W2 double buffers, [4096,6144) as reduce buf
//   [8192,24576)  sH [64][256]; first 4096 floats double as W1 buffers (GEMM1)
//   [24576,...]   sM[64], sR[64], sN[64], cnt

__global__ __launch_bounds__(BDIM, 2)
void fused_filter_kernel(const float* __restrict__ f_ij,
                         const float* __restrict__ r_ij,
                         const float* __restrict__ nmask,
                         const int*   __restrict__ neigh,
                         const float* __restrict__ W1,
                         const float* __restrict__ b1,
                         const float* __restrict__ W2,
                         const float* __restrict__ b2,
                         const float* __restrict__ XF,
                         float* __restrict__ Y)
{
    extern __shared__ float smem[];
    float* sF   = smem;
    float* sH   = smem + 8192;
    float* sW1a = sH;                 // aliases sH rows 0..7  (dead in GEMM1)
    float* sW1b = sH + 2048;          // aliases sH rows 8..15
    float* sW2a = sF;                 // aliases sF (dead in GEMM2)
    float* sW2b = sF + 2048;
    float* sRed = sF + 4096;          // 2048 floats
    float* sM   = smem + 24576;
    int*   sR   = (int*)(smem + 24640);
    int*   sN   = (int*)(smem + 24704);
    int*   sCnt = (int*)(smem + 24768);

    const int atom = blockIdx.x;
    const int tid  = threadIdx.x;
    const int tn   = tid >> 5;
    const int f0   = (tid & 31) * 8;

    if (tid == 0) *sCnt = 0;
    __syncthreads();
    if (tid < NB) {
        float r = r_ij[atom * NB + tid];
        float m = nmask[atom * NB + tid];
        float eff = (r <= CUTOFF) ? m : 0.0f;
        if (eff != 0.0f) {
            int pos = atomicAdd(sCnt, 1);
            sM[pos] = eff;
            sR[pos] = (atom >> 9) * 512 + neigh[atom * NB + tid];
            sN[pos] = tid;
        }
    }
    __syncthreads();
    const int V = *sCnt;
    const int jcnt = (tn < V) ? ((V - tn + 7) >> 3) : 0;   // rows j*8+tn < V

    // compacted copy of f_ij rows (order irrelevant for the final sum)
    for (int q = tid; q < V * 32; q += BDIM) {
        int pos = q >> 5, c = (q & 31) * 4;
        int n = sN[pos];
        *(float4*)&sF[pos * KS + c] =
            *(const float4*)&f_ij[(size_t)atom * (NB * KS) + n * KS + c];
    }
    // prologue: stage W1 tile 0
    *(float4*)&sW1a[tid * 8]     = *(const float4*)&W1[tid * 8];
    *(float4*)&sW1a[tid * 8 + 4] = *(const float4*)&W1[tid * 8 + 4];
    __syncthreads();

    unsigned long long acc[8][4];
    #pragma unroll
    for (int j = 0; j < 8; ++j)
        #pragma unroll
        for (int i = 0; i < 4; ++i) acc[j][i] = 0ull;

    // ---- GEMM1: P = F @ W1 ----
    #pragma unroll 1
    for (int k0 = 0; k0 < KS; k0 += 8) {
        const float* cur = ((k0 >> 3) & 1) ? sW1b : sW1a;
        float*       nxt = ((k0 >> 3) & 1) ? sW1a : sW1b;
        float4 p0, p1;
        const bool more = (k0 + 8) < KS;
        if (more) {
            p0 = *(const float4*)&W1[(k0 + 8) * 256 + tid * 8];
            p1 = *(const float4*)&W1[(k0 + 8) * 256 + tid * 8 + 4];
        }
        #pragma unroll
        for (int kk = 0; kk < 8; ++kk) {
            ulonglong2 bva = *(const ulonglong2*)&cur[kk * 256 + f0];
            ulonglong2 bvb = *(const ulonglong2*)&cur[kk * 256 + f0 + 4];
            #pragma unroll
            for (int j = 0; j < 8; ++j) {
                if (j >= jcnt) break;
                unsigned long long a2 = pack_dup(sF[(j * 8 + tn) * KS + k0 + kk]);
                fma2(acc[j][0], a2, bva.x);
                fma2(acc[j][1], a2, bva.y);
                fma2(acc[j][2], a2, bvb.x);
                fma2(acc[j][3], a2, bvb.y);
            }
        }
        if (more) {
            *(float4*)&nxt[tid * 8]     = p0;
            *(float4*)&nxt[tid * 8 + 4] = p1;
        }
        __syncthreads();
    }

    // epilogue: H = ssp(P + b1) into sH (safe: W1 buffers dead after last sync)
    {
        float4 ba  = *(const float4*)&b1[f0];
        float4 bb4 = *(const float4*)&b1[f0 + 4];
        float bb[8] = {ba.x, ba.y, ba.z, ba.w, bb4.x, bb4.y, bb4.z, bb4.w};
        #pragma unroll
        for (int j = 0; j < 8; ++j) {
            if (j >= jcnt) break;
            float h[8];
            #pragma unroll
            for (int i2 = 0; i2 < 4; ++i2) {
                float2 v = unpack2(acc[j][i2]);
                h[2*i2]   = sspf(v.x + bb[2*i2]);
                h[2*i2+1] = sspf(v.y + bb[2*i2+1]);
            }
            *(float4*)&sH[(j * 8 + tn) * NF + f0]     = make_float4(h[0], h[1], h[2], h[3]);
            *(float4*)&sH[(j * 8 + tn) * NF + f0 + 4] = make_float4(h[4], h[5], h[6], h[7]);
        }
    }
    // stage W2 tile 0 into sF-region buffers (sF dead now)
    __syncthreads();
    *(float4*)&sW2a[tid * 8]     = *(const float4*)&W2[tid * 8];
    *(float4*)&sW2a[tid * 8 + 4] = *(const float4*)&W2[tid * 8 + 4];

    #pragma unroll
    for (int j = 0; j < 8; ++j)
        #pragma unroll
        for (int i = 0; i < 4; ++i) acc[j][i] = 0ull;
    __syncthreads();

    // ---- GEMM2: Wf = H @ W2 ----
    #pragma unroll 1
    for (int k0 = 0; k0 < NF; k0 += 8) {
        const float* cur = ((k0 >> 3) & 1) ? sW2b : sW2a;
        float*       nxt = ((k0 >> 3) & 1) ? sW2a : sW2b;
        float4 p0, p1;
        const bool more = (k0 + 8) < NF;
        if (more) {
            p0 = *(const float4*)&W2[(k0 + 8) * 256 + tid * 8];
            p1 = *(const float4*)&W2[(k0 + 8) * 256 + tid * 8 + 4];
        }
        #pragma unroll
        for (int kk = 0; kk < 8; ++kk) {
            ulonglong2 bva = *(const ulonglong2*)&cur[kk * 256 + f0];
            ulonglong2 bvb = *(const ulonglong2*)&cur[kk * 256 + f0 + 4];
            #pragma unroll
            for (int j = 0; j < 8; ++j) {
                if (j >= jcnt) break;
                unsigned long long a2 = pack_dup(sH[(j * 8 + tn) * NF + k0 + kk]);
                fma2(acc[j][0], a2, bva.x);
                fma2(acc[j][1], a2, bva.y);
                fma2(acc[j][2], a2, bvb.x);
                fma2(acc[j][3], a2, bvb.y);
            }
        }
        if (more) {
            *(float4*)&nxt[tid * 8]     = p0;
            *(float4*)&nxt[tid * 8 + 4] = p1;
        }
        __syncthreads();
    }

    // epilogue: partial y += m * (Wf + b2) * XF[neighbor]
    float part[8];
    #pragma unroll
    for (int i = 0; i < 8; ++i) part[i] = 0.0f;
    {
        float4 ba  = *(const float4*)&b2[f0];
        float4 bb4 = *(const float4*)&b2[f0 + 4];
        float bb[8] = {ba.x, ba.y, ba.z, ba.w, bb4.x, bb4.y, bb4.z, bb4.w};
        #pragma unroll
        for (int j = 0; j < 8; ++j) {
            if (j >= jcnt) break;
            const int pos = j * 8 + tn;
            const float m = sM[pos];
            const float* xr = XF + (size_t)sR[pos] * NF + f0;
            float4 xa = *(const float4*)xr;
            float4 xb = *(const float4*)(xr + 4);
            float xv[8] = {xa.x, xa.y, xa.z, xa.w, xb.x, xb.y, xb.z, xb.w};
            #pragma unroll
            for (int i2 = 0; i2 < 4; ++i2) {
                float2 v = unpack2(acc[j][i2]);
                part[2*i2]   = fmaf(m * (v.x + bb[2*i2]),   xv[2*i2],   part[2*i2]);
                part[2*i2+1] = fmaf(m * (v.y + bb[2*i2+1]), xv[2*i2+1], part[2*i2+1]);
            }
        }
    }
    #pragma unroll
    for (int i = 0; i < 8; ++i)
        sRed[tn * NF + f0 + i] = part[i];
    __syncthreads();
    {
        float y = 0.0f;
        #pragma unroll
        for (int g = 0; g < 8; ++g) y += sRed[g * NF + tid];
        Y[(size_t)atom * NF + tid] = y;
    }
}

// ---- K3: fused tail: out = ssp((Y@Wf2o + bf2o)@Wd + G@Wang + bd) -----------

__global__ __launch_bounds__(BDIM, 2)
void tail_kernel(const float* __restrict__ Yin,
                 const float* __restrict__ Gin,
                 const float* __restrict__ W_f2out,
                 const float* __restrict__ b_f2out,
                 const float* __restrict__ W_dense,
                 const float* __restrict__ b_dense,
                 const float* __restrict__ W_ang,
                 float* __restrict__ out)
{
    extern __shared__ float smem[];
    float* sY  = smem;            // 8192
    float* sT  = smem + 8192;     // 8192
    float* sG  = smem + 16384;    // 4096
    float* sWa = smem + 20480;    // 2048
    float* sWb = smem + 22528;    // 2048

    const int tid = threadIdx.x;
    const int tn  = tid >> 5;
    const int f0  = (tid & 31) * 8;
    const int r0  = tn * 4;

    {
        const float* src = Yin + (size_t)blockIdx.x * 32 * 256;
        #pragma unroll
        for (int u = 0; u < 8; ++u)
            *(float4*)&sY[tid * 4 + u * 1024] = *(const float4*)&src[tid * 4 + u * 1024];
        const float* srcg = Gin + (size_t)blockIdx.x * 32 * 128;
        #pragma unroll
        for (int u = 0; u < 4; ++u)
            *(float4*)&sG[tid * 4 + u * 1024] = *(const float4*)&srcg[tid * 4 + u * 1024];
    }
    *(float4*)&sWa[tid * 8]     = *(const float4*)&W_f2out[tid * 8];
    *(float4*)&sWa[tid * 8 + 4] = *(const float4*)&W_f2out[tid * 8 + 4];
    __syncthreads();

    unsigned long long acc[4][4];
    #pragma unroll
    for (int j = 0; j < 4; ++j)
        #pragma unroll
        for (int i = 0; i < 4; ++i) acc[j][i] = 0ull;

    // phase 1: T = Y @ W_f2out + b_f2out
    #pragma unroll 1
    for (int k0 = 0; k0 < 256; k0 += 8) {
        const float* cur = ((k0 >> 3) & 1) ? sWb : sWa;
        float*       nxt = ((k0 >> 3) & 1) ? sWa : sWb;
        float4 p0, p1;
        const bool more = (k0 + 8) < 256;
        if (more) {
            p0 = *(const float4*)&W_f2out[(k0 + 8) * 256 + tid * 8];
            p1 = *(const float4*)&W_f2out[(k0 + 8) * 256 + tid * 8 + 4];
        }
        mma_step<4>(cur, sY + k0, 256, r0, f0, acc);
        if (more) {
            *(float4*)&nxt[tid * 8]     = p0;
            *(float4*)&nxt[tid * 8 + 4] = p1;
        }
        __syncthreads();
    }
    {
        float4 ba  = *(const float4*)&b_f2out[f0];
        float4 bb4 = *(const float4*)&b_f2out[f0 + 4];
        float bb[8] = {ba.x, ba.y, ba.z, ba.w, bb4.x, bb4.y, bb4.z, bb4.w};
        #pragma unroll
        for (int j = 0; j < 4; ++j) {
            float w[8];
            #pragma unroll
            for (int i2 = 0; i2 < 4; ++i2) {
                float2 v = unpack2(acc[j][i2]);
                w[2*i2] = v.x + bb[2*i2]; w[2*i2+1] = v.y + bb[2*i2+1];
            }
            *(float4*)&sT[(r0 + j) * 256 + f0]     = make_float4(w[0], w[1], w[2], w[3]);
            *(float4*)&sT[(r0 + j) * 256 + f0 + 4] = make_float4(w[4], w[5], w[6], w[7]);
        }
    }
    __syncthreads();
    *(float4*)&sWa[tid * 8]     = *(const float4*)&W_dense[tid * 8];
    *(float4*)&sWa[tid * 8 + 4] = *(const float4*)&W_dense[tid * 8 + 4];
    #pragma unroll
    for (int j = 0; j < 4; ++j)
        #pragma unroll
        for (int i = 0; i < 4; ++i) acc[j][i] = 0ull;
    __syncthreads();

    // phase 2a: U = T @ W_dense
    #pragma unroll 1
    for (int k0 = 0; k0 < 256; k0 += 8) {
        const float* cur = ((k0 >> 3) & 1) ? sWb : sWa;
        float*       nxt = ((k0 >> 3) & 1) ? sWa : sWb;
        float4 p0, p1;
        const bool more = (k0 + 8) < 256;
        if (more) {
            p0 = *(const float4*)&W_dense[(k0 + 8) * 256 + tid * 8];
            p1 = *(const float4*)&W_dense[(k0 + 8) * 256 + tid * 8 + 4];
        } else {  // prefetch first W_ang tile instead
            p0 = *(const float4*)&W_ang[tid * 8];
            p1 = *(const float4*)&W_ang[tid * 8 + 4];
        }
        mma_step<4>(cur, sT + k0, 256, r0, f0, acc);
        *(float4*)&nxt[tid * 8]     = p0;
        *(float4*)&nxt[tid * 8 + 4] = p1;
        __syncthreads();
    }
    // phase 2b: U += G @ W_ang  (K=128; buffer parity continues: tile0 in sWa)
    #pragma unroll 1
    for (int k0 = 0; k0 < 128; k0 += 8) {
        const float* cur = ((k0 >> 3) & 1) ? sWb : sWa;
        float*       nxt = ((k0 >> 3) & 1) ? sWa : sWb;
        float4 p0, p1;
        const bool more = (k0 + 8) < 128;
        if (more) {
            p0 = *(const float4*)&W_ang[(k0 + 8) * 256 + tid * 8];
            p1 = *(const float4*)&W_ang[(k0 + 8) * 256 + tid * 8 + 4];
        }
        mma_step<4>(cur, sG + k0, 128, r0, f0, acc);
        if (more) {
            *(float4*)&nxt[tid * 8]     = p0;
            *(float4*)&nxt[tid * 8 + 4] = p1;
        }
        __syncthreads();
    }

    {
        float4 ba  = *(const float4*)&b_dense[f0];
        float4 bb4 = *(const float4*)&b_dense[f0 + 4];
        float bb[8] = {ba.x, ba.y, ba.z, ba.w, bb4.x, bb4.y, bb4.z, bb4.w};
        #pragma unroll
        for (int j = 0; j < 4; ++j) {
            float w[8];
            #pragma unroll
            for (int i2 = 0; i2 < 4; ++i2) {
                float2 v = unpack2(acc[j][i2]);
                w[2*i2]   = sspf(v.x + bb[2*i2]);
                w[2*i2+1] = sspf(v.y + bb[2*i2+1]);
            }
            const int row = blockIdx.x * 32 + r0 + j;
            *(float4*)&out[(size_t)row * 256 + f0]     = make_float4(w[0], w[1], w[2], w[3]);
            *(float4*)&out[(size_t)row * 256 + f0 + 4] = make_float4(w[4], w[5], w[6], w[7]);
        }
    }
}

// ---------------------------------------------------------------------------

extern "C" void kernel_launch(void* const* d_in, const int* in_sizes, int n_in,
                              void* d_out, int out_size)
{
    const float* x        = (const float*)d_in[0];
    const float* r_ij     = (const float*)d_in[1];
    const float* f_ij     = (const float*)d_in[2];
    const float* G_i      = (const float*)d_in[3];
    const float* nmask    = (const float*)d_in[4];
    const int*   neigh    = (const int*)  d_in[5];
    const float* W_in2f   = (const float*)d_in[6];
    const float* W1       = (const float*)d_in[7];
    const float* b1       = (const float*)d_in[8];
    const float* W2       = (const float*)d_in[9];
    const float* b2       = (const float*)d_in[10];
    const float* W_f2out  = (const float*)d_in[11];
    const float* b_f2out  = (const float*)d_in[12];
    const float* W_dense  = (const float*)d_in[13];
    const float* b_dense  = (const float*)d_in[14];
    const float* W_ang    = (const float*)d_in[15];
    float* out = (float*)d_out;

    float *pXF, *pY;
    cudaGetSymbolAddress((void**)&pXF, g_XF);
    cudaGetSymbolAddress((void**)&pY,  g_Y);

    const size_t smem1 = (8192 + 4096) * 4;             // 49,152
    const size_t smem2 = (24576 + 64 + 64 + 64 + 32) * 4; // ~99KB
    const size_t smem3 = (24576) * 4;                   // 98,304

    cudaFuncSetAttribute(gemm32_kernel,
                         cudaFuncAttributeMaxDynamicSharedMemorySize, (int)smem1);
    cudaFuncSetAttribute(fused_filter_kernel,
                         cudaFuncAttributeMaxDynamicSharedMemorySize, (int)smem2);
    cudaFuncSetAttribute(tail_kernel,
                         cudaFuncAttributeMaxDynamicSharedMemorySize, (int)smem3);

    gemm32_kernel<<<NATOMS / 32, BDIM, smem1>>>(x, W_in2f, pXF);
    fused_filter_kernel<<<NATOMS, BDIM, smem2>>>(
        f_ij, r_ij, nmask, neigh, W1, b1, W2, b2, pXF, pY);
    tail_kernel<<<NATOMS / 32, BDIM, smem3>>>(
        pY, G_i, W_f2out, b_f2out, W_dense, b_dense, W_ang, out);
}

// round 3
// speedup vs baseline: 1.3120x; 1.3120x over previous
#include <cuda_runtime.h>
#include <cuda_bf16.h>

// ---------------------------------------------------------------------------
// SchNet interaction block, GB300 sm_103a — FFMA2 (fma.rn.f32x2) pipeline v3.
//   K1: XF = x @ W_in2f                                   (gemm32)
//   K2: per-atom fused filter MLP + gather + aggregate    (fused_filter)
//   K3: out = ssp((Y@W_f2out+b_f2out)@W_dense + G@W_ang + b_dense)  (tail)
// v3: flat unrolled MMA body (no dynamic trip counts), double-buffered
//     weight staging, float4 A-operand loads, fused tail.
// ---------------------------------------------------------------------------

#define BDIM 256
#define NB   64
#define KS   128
#define NF   256
#define NATOMS 4096
#define CUTOFF 5.0f

__device__ float g_XF[NATOMS * NF];
__device__ float g_Y [NATOMS * NF];

// ---- packed f32x2 helpers --------------------------------------------------

__device__ __forceinline__ void fma2(unsigned long long& d,
                                     unsigned long long a,
                                     unsigned long long b) {
    asm("fma.rn.f32x2 %0, %1, %2, %3;" : "=l"(d) : "l"(a), "l"(b), "l"(d));
}
__device__ __forceinline__ unsigned long long pack_dup(float v) {
    unsigned long long r;
    asm("mov.b64 %0, {%1, %1};" : "=l"(r) : "f"(v));
    return r;
}
__device__ __forceinline__ float2 unpack2(unsigned long long u) {
    float2 r;
    asm("mov.b64 {%0, %1}, %2;" : "=f"(r.x), "=f"(r.y) : "l"(u));
    return r;
}
__device__ __forceinline__ float f4c(const float4& v, int i) {
    return i == 0 ? v.x : i == 1 ? v.y : i == 2 ? v.z : v.w;
}
__device__ __forceinline__ float sspf(float v) {
    float e = __expf(v);
    float r = __logf(fmaf(0.5f, e, 0.5f));
    return (v > 60.0f) ? (v - 0.69314718055994531f) : r;
}

// ---- shared 8-deep MMA tile: acc[j][*] += A[rowbase+j, 0..7] * Wtile -------
// cur: staged 8x256 weight tile.  sA: A rows (lda floats), pre-offset by k0.

template<int JROWS>
__device__ __forceinline__ void mma_tile8(const float* cur, const float* sA,
                                          int lda, int rowbase, int f0,
                                          unsigned long long (&acc)[JROWS][4])
{
    #pragma unroll
    for (int kq = 0; kq < 8; kq += 4) {
        float4 av[JROWS];
        #pragma unroll
        for (int j = 0; j < JROWS; ++j)
            av[j] = *(const float4*)&sA[(rowbase + j) * lda + kq];
        #pragma unroll
        for (int kk = 0; kk < 4; ++kk) {
            ulonglong2 bva = *(const ulonglong2*)&cur[(kq + kk) * 256 + f0];
            ulonglong2 bvb = *(const ulonglong2*)&cur[(kq + kk) * 256 + f0 + 4];
            #pragma unroll
            for (int j = 0; j < JROWS; ++j) {
                unsigned long long a2 = pack_dup(f4c(av[j], kk));
                fma2(acc[j][0], a2, bva.x);
                fma2(acc[j][1], a2, bva.y);
                fma2(acc[j][2], a2, bvb.x);
                fma2(acc[j][3], a2, bvb.y);
            }
        }
    }
}

// ---- K1: 32-row GEMM, C = A @ W  (K=256, N=256) ----------------------------

__global__ __launch_bounds__(BDIM, 2)
void gemm32_kernel(const float* __restrict__ A,
                   const float* __restrict__ W,
                   float* __restrict__ C)
{
    extern __shared__ float smem[];
    float* sA  = smem;           // 32*256 = 8192
    float* sWa = smem + 8192;    // 2048
    float* sWb = smem + 10240;   // 2048

    const int tid = threadIdx.x;
    const int tn  = tid >> 5;
    const int f0  = (tid & 31) * 8;
    const int r0  = tn * 4;

    {
        const float* src = A + (size_t)blockIdx.x * 32 * 256;
        #pragma unroll
        for (int u = 0; u < 8; ++u)
            *(float4*)&sA[tid * 4 + u * 1024] = *(const float4*)&src[tid * 4 + u * 1024];
    }
    *(float4*)&sWa[tid * 8]     = *(const float4*)&W[tid * 8];
    *(float4*)&sWa[tid * 8 + 4] = *(const float4*)&W[tid * 8 + 4];
    __syncthreads();

    unsigned long long acc[4][4];
    #pragma unroll
    for (int j = 0; j < 4; ++j)
        #pragma unroll
        for (int i = 0; i < 4; ++i) acc[j][i] = 0ull;

    #pragma unroll 1
    for (int k0 = 0; k0 < 256; k0 += 8) {
        const float* cur = ((k0 >> 3) & 1) ? sWb : sWa;
        float*       nxt = ((k0 >> 3) & 1) ? sWa : sWb;
        float4 p0, p1;
        const bool more = (k0 + 8) < 256;
        if (more) {
            p0 = *(const float4*)&W[(k0 + 8) * 256 + tid * 8];
            p1 = *(const float4*)&W[(k0 + 8) * 256 + tid * 8 + 4];
        }
        mma_tile8<4>(cur, sA + k0, 256, r0, f0, acc);
        if (more) {
            *(float4*)&nxt[tid * 8]     = p0;
            *(float4*)&nxt[tid * 8 + 4] = p1;
        }
        __syncthreads();
    }

    #pragma unroll
    for (int j = 0; j < 4; ++j) {
        float w[8];
        #pragma unroll
        for (int i2 = 0; i2 < 4; ++i2) {
            float2 v = unpack2(acc[j][i2]);
            w[2*i2] = v.x; w[2*i2+1] = v.y;
        }
        const int row = blockIdx.x * 32 + r0 + j;
        *(float4*)&C[(size_t)row * 256 + f0]     = make_float4(w[0], w[1], w[2], w[3]);
        *(float4*)&C[(size_t)row * 256 + f0 + 4] = make_float4(w[4], w[5], w[6], w[7]);
    }
}

// ---- K2: fused filter MLP + gather + aggregate, 1 CTA per atom -------------
// smem (floats): sF[0,8192) f_ij tile; during GEMM2 its first 4096 floats are
// W2 double buffers and [4096,6144) the reduce buffer.  sH[8192,24576): H;
// its first 4096 floats double as W1 buffers during GEMM1.  Then sM, sR.

__global__ __launch_bounds__(BDIM, 2)
void fused_filter_kernel(const float* __restrict__ f_ij,
                         const float* __restrict__ r_ij,
                         const float* __restrict__ nmask,
                         const int*   __restrict__ neigh,
                         const float* __restrict__ W1,
                         const float* __restrict__ b1,
                         const float* __restrict__ W2,
                         const float* __restrict__ b2,
                         const float* __restrict__ XF,
                         float* __restrict__ Y)
{
    extern __shared__ float smem[];
    float* sF   = smem;
    float* sH   = smem + 8192;
    float* sW1a = sH;                 // aliases sH rows 0..7
    float* sW1b = sH + 2048;          // aliases sH rows 8..15
    float* sW2a = sF;                 // aliases sF (dead during GEMM2)
    float* sW2b = sF + 2048;
    float* sRed = sF + 4096;          // 2048 floats
    float* sM   = smem + 24576;       // 64
    int*   sR   = (int*)(smem + 24640); // 64

    const int atom = blockIdx.x;
    const int tid  = threadIdx.x;
    const int tn   = tid >> 5;
    const int f0   = (tid & 31) * 8;
    const int n0   = tn * 8;

    // stage f_ij tile [64,128], masks, neighbor rows
    {
        const float* src = f_ij + (size_t)atom * (NB * KS);
        #pragma unroll
        for (int u = 0; u < 8; ++u)
            *(float4*)&sF[tid * 4 + u * 1024] = *(const float4*)&src[tid * 4 + u * 1024];
    }
    if (tid < NB) {
        float r = r_ij[atom * NB + tid];
        float m = nmask[atom * NB + tid];
        sM[tid] = (r <= CUTOFF) ? m : 0.0f;
        sR[tid] = (atom >> 9) * 512 + neigh[atom * NB + tid];
    }
    // stage W1 tile 0
    *(float4*)&sW1a[tid * 8]     = *(const float4*)&W1[tid * 8];
    *(float4*)&sW1a[tid * 8 + 4] = *(const float4*)&W1[tid * 8 + 4];
    __syncthreads();

    unsigned long long acc[8][4];
    #pragma unroll
    for (int j = 0; j < 8; ++j)
        #pragma unroll
        for (int i = 0; i < 4; ++i) acc[j][i] = 0ull;

    // ---- GEMM1: P = F @ W1 ----
    #pragma unroll 1
    for (int k0 = 0; k0 < KS; k0 += 8) {
        const float* cur = ((k0 >> 3) & 1) ? sW1b : sW1a;
        float*       nxt = ((k0 >> 3) & 1) ? sW1a : sW1b;
        float4 p0, p1;
        const bool more = (k0 + 8) < KS;
        if (more) {
            p0 = *(const float4*)&W1[(k0 + 8) * 256 + tid * 8];
            p1 = *(const float4*)&W1[(k0 + 8) * 256 + tid * 8 + 4];
        }
        mma_tile8<8>(cur, sF + k0, KS, n0, f0, acc);
        if (more) {
            *(float4*)&nxt[tid * 8]     = p0;
            *(float4*)&nxt[tid * 8 + 4] = p1;
        }
        __syncthreads();
    }

    // epilogue: H = ssp(P + b1) into sH (W1 buffers dead after final sync)
    {
        float4 ba  = *(const float4*)&b1[f0];
        float4 bb4 = *(const float4*)&b1[f0 + 4];
        float bb[8] = {ba.x, ba.y, ba.z, ba.w, bb4.x, bb4.y, bb4.z, bb4.w};
        #pragma unroll
        for (int j = 0; j < 8; ++j) {
            float h[8];
            #pragma unroll
            for (int i2 = 0; i2 < 4; ++i2) {
                float2 v = unpack2(acc[j][i2]);
                h[2*i2]   = sspf(v.x + bb[2*i2]);
                h[2*i2+1] = sspf(v.y + bb[2*i2+1]);
            }
            *(float4*)&sH[(n0 + j) * NF + f0]     = make_float4(h[0], h[1], h[2], h[3]);
            *(float4*)&sH[(n0 + j) * NF + f0 + 4] = make_float4(h[4], h[5], h[6], h[7]);
        }
    }
    __syncthreads();
    // stage W2 tile 0 into sF-region buffers (sF dead now)
    *(float4*)&sW2a[tid * 8]     = *(const float4*)&W2[tid * 8];
    *(float4*)&sW2a[tid * 8 + 4] = *(const float4*)&W2[tid * 8 + 4];

    #pragma unroll
    for (int j = 0; j < 8; ++j)
        #pragma unroll
        for (int i = 0; i < 4; ++i) acc[j][i] = 0ull;
    __syncthreads();

    // ---- GEMM2: Wf = H @ W2 ----
    #pragma unroll 1
    for (int k0 = 0; k0 < NF; k0 += 8) {
        const float* cur = ((k0 >> 3) & 1) ? sW2b : sW2a;
        float*       nxt = ((k0 >> 3) & 1) ? sW2a : sW2b;
        float4 p0, p1;
        const bool more = (k0 + 8) < NF;
        if (more) {
            p0 = *(const float4*)&W2[(k0 + 8) * 256 + tid * 8];
            p1 = *(const float4*)&W2[(k0 + 8) * 256 + tid * 8 + 4];
        }
        mma_tile8<8>(cur, sH + k0, NF, n0, f0, acc);
        if (more) {
            *(float4*)&nxt[tid * 8]     = p0;
            *(float4*)&nxt[tid * 8 + 4] = p1;
        }
        __syncthreads();
    }

    // epilogue: partial y += m * (Wf + b2) * XF[neighbor]
    float part[8];
    #pragma unroll
    for (int i = 0; i < 8; ++i) part[i] = 0.0f;
    {
        float4 ba  = *(const float4*)&b2[f0];
        float4 bb4 = *(const float4*)&b2[f0 + 4];
        float bb[8] = {ba.x, ba.y, ba.z, ba.w, bb4.x, bb4.y, bb4.z, bb4.w};
        #pragma unroll
        for (int j = 0; j < 8; ++j) {
            const int n = n0 + j;
            const float m = sM[n];              // warp-uniform
            if (m != 0.0f) {
                const float* xr = XF + (size_t)sR[n] * NF + f0;
                float4 xa = *(const float4*)xr;
                float4 xb = *(const float4*)(xr + 4);
                float xv[8] = {xa.x, xa.y, xa.z, xa.w, xb.x, xb.y, xb.z, xb.w};
                #pragma unroll
                for (int i2 = 0; i2 < 4; ++i2) {
                    float2 v = unpack2(acc[j][i2]);
                    part[2*i2]   = fmaf(m * (v.x + bb[2*i2]),   xv[2*i2],   part[2*i2]);
                    part[2*i2+1] = fmaf(m * (v.y + bb[2*i2+1]), xv[2*i2+1], part[2*i2+1]);
                }
            }
        }
    }
    #pragma unroll
    for (int i = 0; i < 8; ++i)
        sRed[tn * NF + f0 + i] = part[i];
    __syncthreads();
    {
        float y = 0.0f;
        #pragma unroll
        for (int g = 0; g < 8; ++g) y += sRed[g * NF + tid];
        Y[(size_t)atom * NF + tid] = y;
    }
}

// ---- K3: fused tail: out = ssp((Y@Wf2o + bf2o)@Wd + G@Wang + bd) -----------

__global__ __launch_bounds__(BDIM, 2)
void tail_kernel(const float* __restrict__ Yin,
                 const float* __restrict__ Gin,
                 const float* __restrict__ W_f2out,
                 const float* __restrict__ b_f2out,
                 const float* __restrict__ W_dense,
                 const float* __restrict__ b_dense,
                 const float* __restrict__ W_ang,
                 float* __restrict__ out)
{
    extern __shared__ float smem[];
    float* sY  = smem;            // 8192
    float* sT  = smem + 8192;     // 8192
    float* sG  = smem + 16384;    // 4096
    float* sWa = smem + 20480;    // 2048
    float* sWb = smem + 22528;    // 2048

    const int tid = threadIdx.x;
    const int tn  = tid >> 5;
    const int f0  = (tid & 31) * 8;
    const int r0  = tn * 4;

    {
        const float* src = Yin + (size_t)blockIdx.x * 32 * 256;
        #pragma unroll
        for (int u = 0; u < 8; ++u)
            *(float4*)&sY[tid * 4 + u * 1024] = *(const float4*)&src[tid * 4 + u * 1024];
        const float* srcg = Gin + (size_t)blockIdx.x * 32 * 128;
        #pragma unroll
        for (int u = 0; u < 4; ++u)
            *(float4*)&sG[tid * 4 + u * 1024] = *(const float4*)&srcg[tid * 4 + u * 1024];
    }
    *(float4*)&sWa[tid * 8]     = *(const float4*)&W_f2out[tid * 8];
    *(float4*)&sWa[tid * 8 + 4] = *(const float4*)&W_f2out[tid * 8 + 4];
    __syncthreads();

    unsigned long long acc[4][4];
    #pragma unroll
    for (int j = 0; j < 4; ++j)
        #pragma unroll
        for (int i = 0; i < 4; ++i) acc[j][i] = 0ull;

    // phase 1: T = Y @ W_f2out + b_f2out
    #pragma unroll 1
    for (int k0 = 0; k0 < 256; k0 += 8) {
        const float* cur = ((k0 >> 3) & 1) ? sWb : sWa;
        float*       nxt = ((k0 >> 3) & 1) ? sWa : sWb;
        float4 p0, p1;
        const bool more = (k0 + 8) < 256;
        if (more) {
            p0 = *(const float4*)&W_f2out[(k0 + 8) * 256 + tid * 8];
            p1 = *(const float4*)&W_f2out[(k0 + 8) * 256 + tid * 8 + 4];
        }
        mma_tile8<4>(cur, sY + k0, 256, r0, f0, acc);
        if (more) {
            *(float4*)&nxt[tid * 8]     = p0;
            *(float4*)&nxt[tid * 8 + 4] = p1;
        }
        __syncthreads();
    }
    {
        float4 ba  = *(const float4*)&b_f2out[f0];
        float4 bb4 = *(const float4*)&b_f2out[f0 + 4];
        float bb[8] = {ba.x, ba.y, ba.z, ba.w, bb4.x, bb4.y, bb4.z, bb4.w};
        #pragma unroll
        for (int j = 0; j < 4; ++j) {
            float w[8];
            #pragma unroll
            for (int i2 = 0; i2 < 4; ++i2) {
                float2 v = unpack2(acc[j][i2]);
                w[2*i2] = v.x + bb[2*i2]; w[2*i2+1] = v.y + bb[2*i2+1];
            }
            *(float4*)&sT[(r0 + j) * 256 + f0]     = make_float4(w[0], w[1], w[2], w[3]);
            *(float4*)&sT[(r0 + j) * 256 + f0 + 4] = make_float4(w[4], w[5], w[6], w[7]);
        }
    }
    __syncthreads();
    *(float4*)&sWa[tid * 8]     = *(const float4*)&W_dense[tid * 8];
    *(float4*)&sWa[tid * 8 + 4] = *(const float4*)&W_dense[tid * 8 + 4];
    #pragma unroll
    for (int j = 0; j < 4; ++j)
        #pragma unroll
        for (int i = 0; i < 4; ++i) acc[j][i] = 0ull;
    __syncthreads();

    // phase 2a: U = T @ W_dense
    #pragma unroll 1
    for (int k0 = 0; k0 < 256; k0 += 8) {
        const float* cur = ((k0 >> 3) & 1) ? sWb : sWa;
        float*       nxt = ((k0 >> 3) & 1) ? sWa : sWb;
        float4 p0, p1;
        const bool more = (k0 + 8) < 256;
        if (more) {
            p0 = *(const float4*)&W_dense[(k0 + 8) * 256 + tid * 8];
            p1 = *(const float4*)&W_dense[(k0 + 8) * 256 + tid * 8 + 4];
        } else {  // prefetch first W_ang tile instead
            p0 = *(const float4*)&W_ang[tid * 8];
            p1 = *(const float4*)&W_ang[tid * 8 + 4];
        }
        mma_tile8<4>(cur, sT + k0, 256, r0, f0, acc);
        *(float4*)&nxt[tid * 8]     = p0;
        *(float4*)&nxt[tid * 8 + 4] = p1;
        __syncthreads();
    }
    // phase 2b: U += G @ W_ang  (K=128)
    #pragma unroll 1
    for (int k0 = 0; k0 < 128; k0 += 8) {
        const float* cur = ((k0 >> 3) & 1) ? sWb : sWa;
        float*       nxt = ((k0 >> 3) & 1) ? sWa : sWb;
        float4 p0, p1;
        const bool more = (k0 + 8) < 128;
        if (more) {
            p0 = *(const float4*)&W_ang[(k0 + 8) * 256 + tid * 8];
            p1 = *(const float4*)&W_ang[(k0 + 8) * 256 + tid * 8 + 4];
        }
        mma_tile8<4>(cur, sG + k0, 128, r0, f0, acc);
        if (more) {
            *(float4*)&nxt[tid * 8]     = p0;
            *(float4*)&nxt[tid * 8 + 4] = p1;
        }
        __syncthreads();
    }

    {
        float4 ba  = *(const float4*)&b_dense[f0];
        float4 bb4 = *(const float4*)&b_dense[f0 + 4];
        float bb[8] = {ba.x, ba.y, ba.z, ba.w, bb4.x, bb4.y, bb4.z, bb4.w};
        #pragma unroll
        for (int j = 0; j < 4; ++j) {
            float w[8];
            #pragma unroll
            for (int i2 = 0; i2 < 4; ++i2) {
                float2 v = unpack2(acc[j][i2]);
                w[2*i2]   = sspf(v.x + bb[2*i2]);
                w[2*i2+1] = sspf(v.y + bb[2*i2+1]);
            }
            const int row = blockIdx.x * 32 + r0 + j;
            *(float4*)&out[(size_t)row * 256 + f0]     = make_float4(w[0], w[1], w[2], w[3]);
            *(float4*)&out[(size_t)row * 256 + f0 + 4] = make_float4(w[4], w[5], w[6], w[7]);
        }
    }
}

// ---------------------------------------------------------------------------

extern "C" void kernel_launch(void* const* d_in, const int* in_sizes, int n_in,
                              void* d_out, int out_size)
{
    const float* x        = (const float*)d_in[0];
    const float* r_ij     = (const float*)d_in[1];
    const float* f_ij     = (const float*)d_in[2];
    const float* G_i      = (const float*)d_in[3];
    const float* nmask    = (const float*)d_in[4];
    const int*   neigh    = (const int*)  d_in[5];
    const float* W_in2f   = (const float*)d_in[6];
    const float* W1       = (const float*)d_in[7];
    const float* b1       = (const float*)d_in[8];
    const float* W2       = (const float*)d_in[9];
    const float* b2       = (const float*)d_in[10];
    const float* W_f2out  = (const float*)d_in[11];
    const float* b_f2out  = (const float*)d_in[12];
    const float* W_dense  = (const float*)d_in[13];
    const float* b_dense  = (const float*)d_in[14];
    const float* W_ang    = (const float*)d_in[15];
    float* out = (float*)d_out;

    float *pXF, *pY;
    cudaGetSymbolAddress((void**)&pXF, g_XF);
    cudaGetSymbolAddress((void**)&pY,  g_Y);

    const size_t smem1 = (8192 + 4096) * 4;       // 49,152
    const size_t smem2 = (24576 + 128) * 4;       // 98,816
    const size_t smem3 = (24576) * 4;             // 98,304

    cudaFuncSetAttribute(gemm32_kernel,
                         cudaFuncAttributeMaxDynamicSharedMemorySize, (int)smem1);
    cudaFuncSetAttribute(fused_filter_kernel,
                         cudaFuncAttributeMaxDynamicSharedMemorySize, (int)smem2);
    cudaFuncSetAttribute(tail_kernel,
                         cudaFuncAttributeMaxDynamicSharedMemorySize, (int)smem3);

    gemm32_kernel<<<NATOMS / 32, BDIM, smem1>>>(x, W_in2f, pXF);
    fused_filter_kernel<<<NATOMS, BDIM, smem2>>>(
        f_ij, r_ij, nmask, neigh, W1, b1, W2, b2, pXF, pY);
    tail_kernel<<<NATOMS / 32, BDIM, smem3>>>(
        pY, G_i, W_f2out, b_f2out, W_dense, b_dense, W_ang, out);
}